// round 1
// baseline (speedup 1.0000x reference)
#include <cuda_runtime.h>
#include <cstdint>

// Problem constants (fixed by the reference)
#define SOM_M    32
#define SOM_N    32
#define MN       1024          // 32*32
#define BATCH    2048
#define DIM      128
#define NITER_F  100.0f
#define ALPHA_F  0.3f
#define SIGMA_F  16.0f         // max(M,N)/2

// ---------------- scratch (no allocations allowed) ----------------
__device__ unsigned long long g_bmu[BATCH];     // packed (ordered-d2 << 32) | m
__device__ float g_w2[MN];                      // ||w_m||^2
__device__ float g_S[MN * DIM];                 // sum of x rows per BMU cell
__device__ float g_cnt[MN];                     // count per BMU cell
__device__ float g_T[SOM_M * SOM_N * DIM];      // [cx][by][d] partial contraction
__device__ float g_tc[SOM_M * SOM_N];           // [cx][by] partial count contraction

// monotone float -> uint mapping (preserves < ordering for all finite floats)
__device__ __forceinline__ unsigned int f2ord(float f) {
    unsigned int u = __float_as_uint(f);
    return (u & 0x80000000u) ? ~u : (u | 0x80000000u);
}

// ---------------- K0: reset scratch ----------------
__global__ void k_init() {
    int i = blockIdx.x * blockDim.x + threadIdx.x;   // 0 .. 131071
    if (i < MN * DIM) g_S[i] = 0.0f;
    if (i < BATCH)    g_bmu[i] = 0xFFFFFFFFFFFFFFFFULL;
    if (i < MN)       g_cnt[i] = 0.0f;
}

// ---------------- K0b: w2[m] = ||w_m||^2 (one warp per row) ----------------
__global__ void k_w2(const float* __restrict__ w) {
    int warp = (blockIdx.x * blockDim.x + threadIdx.x) >> 5;  // 0..1023
    int lane = threadIdx.x & 31;
    if (warp >= MN) return;
    float4 v = *(const float4*)&w[warp * DIM + lane * 4];
    float s = v.x * v.x + v.y * v.y + v.z * v.z + v.w * v.w;
    #pragma unroll
    for (int o = 16; o >= 1; o >>= 1) s += __shfl_xor_sync(0xffffffffu, s, o);
    if (lane == 0) g_w2[warp] = s;
}

// ---------------- K1: BMU distance GEMM + argmin ----------------
// tile: 128 m x 32 b per block, 256 threads, each thread 8m x 2b.
// d2'(m,b) = w2[m] - 2 * dot(w[m], x[b])   (x2 dropped: constant per b)
#define WSP 132   // padded row stride (floats), 16B-aligned rows
#define XSP 33

__global__ __launch_bounds__(256, 2)
void k_bmu(const float* __restrict__ x, const float* __restrict__ w) {
    __shared__ float Ws[32 * WSP];   // [kk][m]  transposed W tile
    __shared__ float Xs[32 * XSP];   // [kk][b]  transposed X tile

    const int m0 = blockIdx.x * 128;
    const int b0 = blockIdx.y * 32;
    const int tid = threadIdx.x;
    const int tm = (tid & 15) * 8;   // m offset in tile (8 rows)
    const int tb = (tid >> 4) * 2;   // b offset in tile (2 cols)

    float acc[8][2];
    #pragma unroll
    for (int i = 0; i < 8; i++) { acc[i][0] = 0.0f; acc[i][1] = 0.0f; }

    for (int kc = 0; kc < DIM; kc += 32) {
        __syncthreads();
        // stage W tile transposed: 128 rows x 32 cols
        #pragma unroll
        for (int i = 0; i < 4; i++) {
            int idx = tid + i * 256;         // 0..1023 float4s
            int row = idx >> 3;              // m row 0..127
            int c4  = idx & 7;               // float4 col
            float4 v = *(const float4*)&w[(m0 + row) * DIM + kc + c4 * 4];
            Ws[(c4 * 4 + 0) * WSP + row] = v.x;
            Ws[(c4 * 4 + 1) * WSP + row] = v.y;
            Ws[(c4 * 4 + 2) * WSP + row] = v.z;
            Ws[(c4 * 4 + 3) * WSP + row] = v.w;
        }
        // stage X tile transposed: 32 rows(b) x 32 cols(k)
        {
            int row = tid >> 3;              // b row 0..31
            int c4  = tid & 7;
            float4 v = *(const float4*)&x[(b0 + row) * DIM + kc + c4 * 4];
            Xs[(c4 * 4 + 0) * XSP + row] = v.x;
            Xs[(c4 * 4 + 1) * XSP + row] = v.y;
            Xs[(c4 * 4 + 2) * XSP + row] = v.z;
            Xs[(c4 * 4 + 3) * XSP + row] = v.w;
        }
        __syncthreads();

        #pragma unroll
        for (int kk = 0; kk < 32; kk++) {
            float4 wa = *(const float4*)&Ws[kk * WSP + tm];
            float4 wb = *(const float4*)&Ws[kk * WSP + tm + 4];
            float x0 = Xs[kk * XSP + tb];
            float x1 = Xs[kk * XSP + tb + 1];
            acc[0][0] += wa.x * x0;  acc[0][1] += wa.x * x1;
            acc[1][0] += wa.y * x0;  acc[1][1] += wa.y * x1;
            acc[2][0] += wa.z * x0;  acc[2][1] += wa.z * x1;
            acc[3][0] += wa.w * x0;  acc[3][1] += wa.w * x1;
            acc[4][0] += wb.x * x0;  acc[4][1] += wb.x * x1;
            acc[5][0] += wb.y * x0;  acc[5][1] += wb.y * x1;
            acc[6][0] += wb.z * x0;  acc[6][1] += wb.z * x1;
            acc[7][0] += wb.w * x0;  acc[7][1] += wb.w * x1;
        }
    }

    // epilogue: d2' = w2[m] - 2*dot; pack and argmin-reduce
    float w2r[8];
    #pragma unroll
    for (int i = 0; i < 8; i++) w2r[i] = g_w2[m0 + tm + i];

    #pragma unroll
    for (int j = 0; j < 2; j++) {
        unsigned long long best = 0xFFFFFFFFFFFFFFFFULL;
        #pragma unroll
        for (int i = 0; i < 8; i++) {
            float d2 = w2r[i] - 2.0f * acc[i][j];
            unsigned long long key =
                ((unsigned long long)f2ord(d2) << 32) |
                (unsigned long long)(m0 + tm + i);
            best = min(best, key);
        }
        // reduce across the 16 lanes that share this b
        #pragma unroll
        for (int o = 8; o >= 1; o >>= 1) {
            unsigned long long other = __shfl_xor_sync(0xffffffffu, best, o, 16);
            best = min(best, other);
        }
        if ((tid & 15) == 0)
            atomicMin(&g_bmu[b0 + tb + j], best);
    }
}

// ---------------- K2: scatter x rows into BMU bins ----------------
// 8 warps/block, one warp per batch element
__global__ void k_scatter(const float* __restrict__ x) {
    int warp = (blockIdx.x * blockDim.x + threadIdx.x) >> 5;  // 0..2047
    int lane = threadIdx.x & 31;
    if (warp >= BATCH) return;
    int m = (int)(g_bmu[warp] & 0xFFFFFFFFULL);
    const float* xr = &x[warp * DIM];
    #pragma unroll
    for (int i = 0; i < 4; i++) {
        int d = lane + i * 32;
        atomicAdd(&g_S[m * DIM + d], xr[d]);
    }
    if (lane == 0) atomicAdd(&g_cnt[m], 1.0f);
}

// ---------------- K3: x-direction gaussian contraction ----------------
// T[cx][by][d] = sum_bx Ex(cx,bx) * S[by*32+bx][d] ;  tc likewise with cnt
__global__ void k_contract_x(const int* __restrict__ it) {
    float lr_decay = 1.0f - (float)it[0] / NITER_F;
    float sig = SIGMA_F * lr_decay;
    float inv_s2 = 1.0f / (sig * sig);

    int cx = blockIdx.x & 31;
    int by = blockIdx.x >> 5;
    int d  = threadIdx.x;

    float acc = 0.0f, c = 0.0f;
    #pragma unroll
    for (int bx = 0; bx < 32; bx++) {
        float dx = (float)(cx - bx);
        float e = expf(-dx * dx * inv_s2);
        acc += e * g_S[(by * 32 + bx) * DIM + d];
        c   += e * g_cnt[by * 32 + bx];
    }
    g_T[(cx * 32 + by) * DIM + d] = acc;
    if (d == 0) g_tc[cx * 32 + by] = c;
}

// ---------------- K4: y-direction contraction + final update ----------------
__global__ void k_finish(const float* __restrict__ w,
                         const int* __restrict__ it,
                         float* __restrict__ out) {
    float lr_decay = 1.0f - (float)it[0] / NITER_F;
    float alpha_op = ALPHA_F * lr_decay;
    float sig = SIGMA_F * lr_decay;
    float inv_s2 = 1.0f / (sig * sig);

    int c  = blockIdx.x;         // output cell, loc = (c%32, c/32)
    int cx = c & 31;
    int cy = c >> 5;
    int d  = threadIdx.x;

    float acc = 0.0f, s = 0.0f;
    #pragma unroll
    for (int by = 0; by < 32; by++) {
        float dy = (float)(cy - by);
        float e = expf(-dy * dy * inv_s2);
        acc += e * g_T[(cx * 32 + by) * DIM + d];
        s   += e * g_tc[cx * 32 + by];
    }
    float wv = w[c * DIM + d];
    out[c * DIM + d] = wv + alpha_op * acc - alpha_op * s * wv;
}

// ---------------- launch ----------------
extern "C" void kernel_launch(void* const* d_in, const int* in_sizes, int n_in,
                              void* d_out, int out_size) {
    const float* x   = (const float*)d_in[0];   // [2048,128]
    const float* w   = (const float*)d_in[1];   // [1024,128]
    // d_in[2] = locations (layout is (m%32, m//32) by construction; not needed)
    const int*   it  = (const int*)d_in[3];
    float* out = (float*)d_out;

    k_init<<<512, 256>>>();
    k_w2<<<128, 256>>>(w);
    k_bmu<<<dim3(8, 64), 256>>>(x, w);
    k_scatter<<<256, 256>>>(x);
    k_contract_x<<<1024, 128>>>(it);
    k_finish<<<1024, 128>>>(w, it, out);
}

// round 2
// speedup vs baseline: 2.1228x; 2.1228x over previous
#include <cuda_runtime.h>
#include <cstdint>

// Problem constants (fixed by the reference)
#define SOM_M    32
#define SOM_N    32
#define MN       1024          // 32*32
#define BATCH    2048
#define DIM      128
#define NITER_F  100.0f
#define ALPHA_F  0.3f
#define SIGMA_F  16.0f         // max(M,N)/2

// ---------------- scratch (no allocations allowed) ----------------
__device__ unsigned long long g_bmu[BATCH];     // packed (ordered-d2 << 32) | m
__device__ float g_w2[MN];                      // ||w_m||^2
__device__ float g_S[MN * DIM];                 // sum of x rows per BMU cell
__device__ float g_cnt[MN];                     // count per BMU cell

// monotone float -> uint mapping (preserves < ordering for all finite floats)
__device__ __forceinline__ unsigned int f2ord(float f) {
    unsigned int u = __float_as_uint(f);
    return (u & 0x80000000u) ? ~u : (u | 0x80000000u);
}

__device__ __forceinline__ unsigned long long dupf(float f) {
    unsigned long long r;
    unsigned int u = __float_as_uint(f);
    asm("mov.b64 %0, {%1, %1};" : "=l"(r) : "r"(u));
    return r;
}

__device__ __forceinline__ void ffma2(unsigned long long& acc,
                                      unsigned long long a,
                                      unsigned long long b) {
    asm("fma.rn.f32x2 %0, %1, %2, %0;" : "+l"(acc) : "l"(a), "l"(b));
}

// ---------------- K0: reset scratch + w2 = ||w_m||^2, fused ----------------
__global__ void k_prep(const float* __restrict__ w) {
    int i = blockIdx.x * blockDim.x + threadIdx.x;   // 0 .. 131071
    if (i < MN * DIM) g_S[i] = 0.0f;
    if (i < BATCH)    g_bmu[i] = 0xFFFFFFFFFFFFFFFFULL;
    if (i < MN)       g_cnt[i] = 0.0f;

    int warp = i >> 5;                               // 0 .. 4095
    int lane = i & 31;
    if (warp < MN) {
        float4 v = *(const float4*)&w[warp * DIM + lane * 4];
        float s = v.x * v.x + v.y * v.y + v.z * v.z + v.w * v.w;
        #pragma unroll
        for (int o = 16; o >= 1; o >>= 1) s += __shfl_xor_sync(0xffffffffu, s, o);
        if (lane == 0) g_w2[warp] = s;
    }
}

// ---------------- K1: BMU distance GEMM + argmin (f32x2 packed) ----------------
// block tile: 128 m x 64 b, 256 threads, each thread 8m x 4b via FFMA2.
// d2'(m,b) = w2[m] - 2 * dot(w[m], x[b])   (x2 dropped: constant per b)
#define WSP 132   // Ws row stride in floats (16B-aligned rows)
#define XSP 68    // Xs row stride in floats

__global__ __launch_bounds__(256, 2)
void k_bmu(const float* __restrict__ x, const float* __restrict__ w) {
    __shared__ float Ws[32 * WSP];                 // [kk][m]
    __shared__ float Xs[32 * XSP];                 // [kk][b]
    __shared__ unsigned long long Red[16][64];     // argmin reduction buffer

    const int m0 = blockIdx.x * 128;
    const int b0 = blockIdx.y * 64;
    const int tid = threadIdx.x;
    const int ty = tid >> 4;          // 0..15 -> m group
    const int tx = tid & 15;          // 0..15 -> b group
    const int tm = ty * 8;
    const int tb = tx * 4;

    // acc[p][j]: f32x2 pair for m = tm+2p, tm+2p+1 ; column b0+tb+j
    unsigned long long acc[4][4];
    #pragma unroll
    for (int p = 0; p < 4; p++)
        #pragma unroll
        for (int j = 0; j < 4; j++) acc[p][j] = 0ULL;

    for (int kc = 0; kc < DIM; kc += 32) {
        __syncthreads();
        // stage W tile transposed: 128 rows(m) x 32 cols(k)
        #pragma unroll
        for (int i = 0; i < 4; i++) {
            int idx = tid + i * 256;          // 0..1023 float4s
            int row = idx >> 3;               // m row 0..127
            int c4  = idx & 7;                // float4 col
            float4 v = *(const float4*)&w[(m0 + row) * DIM + kc + c4 * 4];
            Ws[(c4 * 4 + 0) * WSP + row] = v.x;
            Ws[(c4 * 4 + 1) * WSP + row] = v.y;
            Ws[(c4 * 4 + 2) * WSP + row] = v.z;
            Ws[(c4 * 4 + 3) * WSP + row] = v.w;
        }
        // stage X tile transposed: 64 rows(b) x 32 cols(k)
        #pragma unroll
        for (int i = 0; i < 2; i++) {
            int idx = tid + i * 256;          // 0..511 float4s
            int row = idx >> 3;               // b row 0..63
            int c4  = idx & 7;
            float4 v = *(const float4*)&x[(b0 + row) * DIM + kc + c4 * 4];
            Xs[(c4 * 4 + 0) * XSP + row] = v.x;
            Xs[(c4 * 4 + 1) * XSP + row] = v.y;
            Xs[(c4 * 4 + 2) * XSP + row] = v.z;
            Xs[(c4 * 4 + 3) * XSP + row] = v.w;
        }
        __syncthreads();

        #pragma unroll 8
        for (int kk = 0; kk < 32; kk++) {
            // w pairs come packed straight out of the 128-bit shared loads
            ulonglong2 wp01 = *(const ulonglong2*)&Ws[kk * WSP + tm];
            ulonglong2 wp23 = *(const ulonglong2*)&Ws[kk * WSP + tm + 4];
            float4 xv = *(const float4*)&Xs[kk * XSP + tb];
            unsigned long long xd0 = dupf(xv.x);
            unsigned long long xd1 = dupf(xv.y);
            unsigned long long xd2 = dupf(xv.z);
            unsigned long long xd3 = dupf(xv.w);
            ffma2(acc[0][0], wp01.x, xd0); ffma2(acc[0][1], wp01.x, xd1);
            ffma2(acc[0][2], wp01.x, xd2); ffma2(acc[0][3], wp01.x, xd3);
            ffma2(acc[1][0], wp01.y, xd0); ffma2(acc[1][1], wp01.y, xd1);
            ffma2(acc[1][2], wp01.y, xd2); ffma2(acc[1][3], wp01.y, xd3);
            ffma2(acc[2][0], wp23.x, xd0); ffma2(acc[2][1], wp23.x, xd1);
            ffma2(acc[2][2], wp23.x, xd2); ffma2(acc[2][3], wp23.x, xd3);
            ffma2(acc[3][0], wp23.y, xd0); ffma2(acc[3][1], wp23.y, xd1);
            ffma2(acc[3][2], wp23.y, xd2); ffma2(acc[3][3], wp23.y, xd3);
        }
    }

    // epilogue: d2' = w2[m] - 2*dot; pack keys, per-thread min over 8 m
    float w2r[8];
    #pragma unroll
    for (int i = 0; i < 8; i++) w2r[i] = g_w2[m0 + tm + i];

    #pragma unroll
    for (int j = 0; j < 4; j++) {
        unsigned long long best = 0xFFFFFFFFFFFFFFFFULL;
        #pragma unroll
        for (int p = 0; p < 4; p++) {
            float lo = __uint_as_float((unsigned int)(acc[p][j]));
            float hi = __uint_as_float((unsigned int)(acc[p][j] >> 32));
            float d2a = w2r[2 * p]     - 2.0f * lo;
            float d2b = w2r[2 * p + 1] - 2.0f * hi;
            unsigned long long ka = ((unsigned long long)f2ord(d2a) << 32)
                                  | (unsigned long long)(m0 + tm + 2 * p);
            unsigned long long kb = ((unsigned long long)f2ord(d2b) << 32)
                                  | (unsigned long long)(m0 + tm + 2 * p + 1);
            best = min(best, min(ka, kb));
        }
        Red[ty][tb + j] = best;
    }
    __syncthreads();

    if (tid < 64) {
        unsigned long long best = Red[0][tid];
        #pragma unroll
        for (int t = 1; t < 16; t++) best = min(best, Red[t][tid]);
        atomicMin(&g_bmu[b0 + tid], best);
    }
}

// ---------------- K2: scatter x rows into BMU bins (vector red) ----------------
__global__ void k_scatter(const float* __restrict__ x) {
    int warp = (blockIdx.x * blockDim.x + threadIdx.x) >> 5;  // 0..2047
    int lane = threadIdx.x & 31;
    if (warp >= BATCH) return;
    int m = (int)(g_bmu[warp] & 0xFFFFFFFFULL);
    float4 v = *(const float4*)&x[warp * DIM + lane * 4];
    float* dst = &g_S[m * DIM + lane * 4];
    asm volatile("red.global.add.v4.f32 [%0], {%1, %2, %3, %4};"
                 :: "l"(dst), "f"(v.x), "f"(v.y), "f"(v.z), "f"(v.w)
                 : "memory");
    if (lane == 0) atomicAdd(&g_cnt[m], 1.0f);
}

// ---------------- K3: fused separable gaussian contraction + update ----------------
// block = (cx, d-quarter): stage A contracts over bx into shared T, stage B
// contracts over by and writes the final weight update.
__global__ __launch_bounds__(256)
void k_tail(const float* __restrict__ w,
            const int* __restrict__ it,
            float* __restrict__ out) {
    __shared__ float Ts[32][36];     // [by][d-local], padded, 16B-aligned rows
    __shared__ float tc_s[32];
    __shared__ float e_s[32];

    const int cx = blockIdx.x & 31;
    const int d0 = (blockIdx.x >> 5) * 32;   // d-quarter base
    const int tid = threadIdx.x;

    float lr_decay = 1.0f - (float)it[0] / NITER_F;
    float alpha_op = ALPHA_F * lr_decay;
    float sig = SIGMA_F * lr_decay;
    float inv_s2 = 1.0f / (sig * sig);

    if (tid < 32) e_s[tid] = expf(-(float)(tid * tid) * inv_s2);
    __syncthreads();

    // stage A: T[by][d] = sum_bx e(|cx-bx|) * S[by*32+bx][d]
    {
        int by = tid >> 3;           // 0..31
        int dq = tid & 7;            // float4 index 0..7
        int d  = d0 + dq * 4;
        float4 a = make_float4(0.f, 0.f, 0.f, 0.f);
        #pragma unroll
        for (int bx = 0; bx < 32; bx++) {
            float e = e_s[abs(cx - bx)];
            float4 s = *(const float4*)&g_S[(by * 32 + bx) * DIM + d];
            a.x += e * s.x; a.y += e * s.y; a.z += e * s.z; a.w += e * s.w;
        }
        *(float4*)&Ts[by][dq * 4] = a;
    }
    if (tid < 32) {
        int by = tid;
        float c = 0.0f;
        #pragma unroll
        for (int bx = 0; bx < 32; bx++)
            c += e_s[abs(cx - bx)] * g_cnt[by * 32 + bx];
        tc_s[by] = c;
    }
    __syncthreads();

    // stage B: out[cy*32+cx][d] = w + alpha*(sum_by e*T[by][d] - (sum_by e*tc)*w)
    {
        int cy = tid >> 3;
        int dq = tid & 7;
        int d  = d0 + dq * 4;
        float4 a = make_float4(0.f, 0.f, 0.f, 0.f);
        float s = 0.0f;
        #pragma unroll
        for (int by = 0; by < 32; by++) {
            float e = e_s[abs(cy - by)];
            float4 t = *(const float4*)&Ts[by][dq * 4];
            a.x += e * t.x; a.y += e * t.y; a.z += e * t.z; a.w += e * t.w;
            s += e * tc_s[by];
        }
        int c = cy * 32 + cx;
        float4 wv = *(const float4*)&w[c * DIM + d];
        float4 o;
        o.x = wv.x + alpha_op * a.x - alpha_op * s * wv.x;
        o.y = wv.y + alpha_op * a.y - alpha_op * s * wv.y;
        o.z = wv.z + alpha_op * a.z - alpha_op * s * wv.z;
        o.w = wv.w + alpha_op * a.w - alpha_op * s * wv.w;
        *(float4*)&out[c * DIM + d] = o;
    }
}

// ---------------- launch ----------------
extern "C" void kernel_launch(void* const* d_in, const int* in_sizes, int n_in,
                              void* d_out, int out_size) {
    const float* x   = (const float*)d_in[0];   // [2048,128]
    const float* w   = (const float*)d_in[1];   // [1024,128]
    // d_in[2] = locations (layout is (m%32, m//32) by construction; not needed)
    const int*   it  = (const int*)d_in[3];
    float* out = (float*)d_out;

    k_prep<<<512, 256>>>(w);
    k_bmu<<<dim3(8, 32), 256>>>(x, w);
    k_scatter<<<256, 256>>>(x);
    k_tail<<<128, 256>>>(w, it, out);
}